// round 5
// baseline (speedup 1.0000x reference)
#include <cuda_runtime.h>
#include <cstdint>

// out[b,h,w,c] = x[b,h,w,c] + (c < 512 ? spatial_pe[h,w,c]
//                                      : pattern_pe[pattern_indices[b,h,w] % 64][c-512])
// x [64,30,30,1024] f32, pattern_indices [64,30,30] i32,
// spatial_pe [30,30,512] f32, pattern_pe [64,512] f32.  H==W==30.
//
// Persistent single-wave launch: 148 SM x 6 blocks = 888 blocks, each
// grid-striding over 14400 four-pixel tiles. Body = R2's front-batched
// 4 x-LDG.128 + 4 PE-LDG.128 per thread (best measured MLP/occ tradeoff),
// with .cs streaming hints on x/out to protect PE residency in L2.

static constexpr int D4    = 256;   // float4 per pixel
static constexpr int HALF4 = 128;   // spatial/pattern split (float4 units)
static constexpr int HW    = 900;   // 30*30
static constexpr int PPT   = 4;     // pixels per tile
static constexpr int NTILE = 64 * HW / PPT;   // 14400
static constexpr int NUM_PAT = 64;
static constexpr int BLOCKS = 148 * 6;        // single resident wave

__global__ void __launch_bounds__(256, 6)
pe_add_kernel(const float4* __restrict__ x4,
              const int*    __restrict__ pidx,
              const float4* __restrict__ sp4,   // [900, 128] float4
              const float4* __restrict__ pp4,   // [64, 128] float4
              float4*       __restrict__ out4)
{
    const int tid = threadIdx.x;
    const bool spatial = (tid < HALF4);
    const int  c      = spatial ? tid : tid - HALF4;

    for (int tt = blockIdx.x; tt < NTILE; tt += BLOCKS) {
        const int pix0 = tt * PPT;
        const int b    = pix0 / HW;          // cheap IMAD sequence
        const int hw0  = pix0 - b * HW;

        const long long i0 = (long long)pix0 * D4 + tid;

        // ---- front-batched x loads (streaming, read-once) ----
        float4 xv0 = __ldcs(&x4[i0 + 0 * D4]);
        float4 xv1 = __ldcs(&x4[i0 + 1 * D4]);
        float4 xv2 = __ldcs(&x4[i0 + 2 * D4]);
        float4 xv3 = __ldcs(&x4[i0 + 3 * D4]);

        // ---- PE loads (L2-resident tables), warp-uniform branch ----
        float4 pe0, pe1, pe2, pe3;
        if (spatial) {                        // warps 0-3
            const float4* s = sp4 + (long long)hw0 * HALF4 + c;
            pe0 = __ldg(&s[0 * HALF4]);
            pe1 = __ldg(&s[1 * HALF4]);
            pe2 = __ldg(&s[2 * HALF4]);
            pe3 = __ldg(&s[3 * HALF4]);
        } else {                              // warps 4-7
            const int4 pi = __ldg(reinterpret_cast<const int4*>(pidx + pix0));
            pe0 = __ldg(&pp4[(long long)(((unsigned)pi.x) % NUM_PAT) * HALF4 + c]);
            pe1 = __ldg(&pp4[(long long)(((unsigned)pi.y) % NUM_PAT) * HALF4 + c]);
            pe2 = __ldg(&pp4[(long long)(((unsigned)pi.z) % NUM_PAT) * HALF4 + c]);
            pe3 = __ldg(&pp4[(long long)(((unsigned)pi.w) % NUM_PAT) * HALF4 + c]);
        }

        xv0.x += pe0.x; xv0.y += pe0.y; xv0.z += pe0.z; xv0.w += pe0.w;
        xv1.x += pe1.x; xv1.y += pe1.y; xv1.z += pe1.z; xv1.w += pe1.w;
        xv2.x += pe2.x; xv2.y += pe2.y; xv2.z += pe2.z; xv2.w += pe2.w;
        xv3.x += pe3.x; xv3.y += pe3.y; xv3.z += pe3.z; xv3.w += pe3.w;

        __stcs(&out4[i0 + 0 * D4], xv0);
        __stcs(&out4[i0 + 1 * D4], xv1);
        __stcs(&out4[i0 + 2 * D4], xv2);
        __stcs(&out4[i0 + 3 * D4], xv3);
    }
}

extern "C" void kernel_launch(void* const* d_in, const int* in_sizes, int n_in,
                              void* d_out, int out_size)
{
    const float4* x4   = (const float4*)d_in[0];
    const int*    pidx = (const int*)d_in[1];
    const float4* sp4  = (const float4*)d_in[2];
    const float4* pp4  = (const float4*)d_in[3];
    float4*       out4 = (float4*)d_out;

    pe_add_kernel<<<BLOCKS, 256>>>(x4, pidx, sp4, pp4, out4);  // 888 blocks
}

// round 6
// speedup vs baseline: 1.1221x; 1.1221x over previous
#include <cuda_runtime.h>
#include <cstdint>

// out[b,h,w,c] = x[b,h,w,c] + (c < 512 ? spatial_pe[h,w,c]
//                                      : pattern_pe[pattern_indices[b,h,w] % 64][c-512])
// x [64,30,30,1024] f32, pattern_indices [64,30,30] i32,
// spatial_pe [30,30,512] f32, pattern_pe [64,512] f32.  H==W==30.
//
// R2 structure (best measured: 6.32 TB/s) + streaming cache hints + grid
// order (batch-fastest) so concurrent CTAs share PE rows in L2.
// Block (256 thr) covers 4 consecutive pixels; thread t owns channel chunk t
// for all 4 pixels: 4 front-batched x LDG.128.cs + 4 PE LDG.128 (L2-resident),
// then 4 STG.128.cs.

static constexpr int D4      = 256;   // float4 per pixel
static constexpr int HALF4   = 128;   // spatial/pattern split (float4 units)
static constexpr int HW      = 900;   // 30*30
static constexpr int PPB     = 4;     // pixels per block
static constexpr int NUM_PAT = 64;

__global__ void __launch_bounds__(256)
pe_add_kernel(const float4* __restrict__ x4,
              const int*    __restrict__ pidx,
              const float4* __restrict__ sp4,   // [900, 128] float4
              const float4* __restrict__ pp4,   // [64, 128] float4
              float4*       __restrict__ out4)
{
    const int tid  = threadIdx.x;
    const int b    = blockIdx.x;                 // batch fastest: concurrent
    const int hw0  = blockIdx.y * PPB;           //  CTAs share PE rows in L2
    const int pix0 = b * HW + hw0;

    const long long i0 = (long long)pix0 * D4 + tid;

    // pattern indices first (dependent gathers issue earliest)
    const int4 pi = __ldg(reinterpret_cast<const int4*>(pidx + pix0));

    // ---- front-batched x loads (streaming: read-once, evict-first) ----
    float4 xv0 = __ldcs(&x4[i0 + 0 * D4]);
    float4 xv1 = __ldcs(&x4[i0 + 1 * D4]);
    float4 xv2 = __ldcs(&x4[i0 + 2 * D4]);
    float4 xv3 = __ldcs(&x4[i0 + 3 * D4]);

    // ---- PE loads (L2-resident tables), warp-uniform branch ----
    float4 pe0, pe1, pe2, pe3;
    if (tid < HALF4) {                           // warps 0-3: spatial half
        const float4* s = sp4 + (long long)hw0 * HALF4 + tid;
        pe0 = __ldg(&s[0 * HALF4]);
        pe1 = __ldg(&s[1 * HALF4]);
        pe2 = __ldg(&s[2 * HALF4]);
        pe3 = __ldg(&s[3 * HALF4]);
    } else {                                     // warps 4-7: pattern half
        const int c = tid - HALF4;
        pe0 = __ldg(&pp4[(long long)(((unsigned)pi.x) % NUM_PAT) * HALF4 + c]);
        pe1 = __ldg(&pp4[(long long)(((unsigned)pi.y) % NUM_PAT) * HALF4 + c]);
        pe2 = __ldg(&pp4[(long long)(((unsigned)pi.z) % NUM_PAT) * HALF4 + c]);
        pe3 = __ldg(&pp4[(long long)(((unsigned)pi.w) % NUM_PAT) * HALF4 + c]);
    }

    xv0.x += pe0.x; xv0.y += pe0.y; xv0.z += pe0.z; xv0.w += pe0.w;
    xv1.x += pe1.x; xv1.y += pe1.y; xv1.z += pe1.z; xv1.w += pe1.w;
    xv2.x += pe2.x; xv2.y += pe2.y; xv2.z += pe2.z; xv2.w += pe2.w;
    xv3.x += pe3.x; xv3.y += pe3.y; xv3.z += pe3.z; xv3.w += pe3.w;

    __stcs(&out4[i0 + 0 * D4], xv0);
    __stcs(&out4[i0 + 1 * D4], xv1);
    __stcs(&out4[i0 + 2 * D4], xv2);
    __stcs(&out4[i0 + 3 * D4], xv3);
}

extern "C" void kernel_launch(void* const* d_in, const int* in_sizes, int n_in,
                              void* d_out, int out_size)
{
    const float4* x4   = (const float4*)d_in[0];
    const int*    pidx = (const int*)d_in[1];
    const float4* sp4  = (const float4*)d_in[2];
    const float4* pp4  = (const float4*)d_in[3];
    float4*       out4 = (float4*)d_out;

    dim3 grid(64, HW / PPB);   // (64 batches, 225 hw-tiles)
    pe_add_kernel<<<grid, 256>>>(x4, pidx, sp4, pp4, out4);
}

// round 7
// speedup vs baseline: 1.1429x; 1.0185x over previous
#include <cuda_runtime.h>
#include <cstdint>

// out[b,h,w,c] = x[b,h,w,c] + (c < 512 ? spatial_pe[h,w,c]
//                                      : pattern_pe[pattern_indices[b,h,w] % 64][c-512])
// x [64,30,30,1024] f32, pattern_indices [64,30,30] i32,
// spatial_pe [30,30,512] f32, pattern_pe [64,512] f32.  H==W==30.
//
// 128-thread blocks, 2 pixels per block. Thread t owns channel chunks t
// (spatial half) and t+128 (pattern half) for both pixels:
//   4 front-batched x LDG.128 (DRAM) + 2 spatial + 2 pattern PE LDG.128 (L2),
//   4 STG.128. Every warp does identical work (no spatial/pattern warp split),
// and 128-thr blocks give finer residency granularity (11-12 blocks/SM).

static constexpr int D4      = 256;   // float4 per pixel
static constexpr int HALF4   = 128;   // spatial/pattern split (float4 units)
static constexpr int HW      = 900;   // 30*30
static constexpr int NPIX    = 64 * HW;          // 57600
static constexpr int NBLK    = NPIX / 2;         // 28800 (2 pixels/block)
static constexpr int NUM_PAT = 64;

__global__ void __launch_bounds__(128, 12)
pe_add_kernel(const float4* __restrict__ x4,
              const int*    __restrict__ pidx,
              const float4* __restrict__ sp4,   // [900, 128] float4
              const float4* __restrict__ pp4,   // [64, 128] float4
              float4*       __restrict__ out4)
{
    const int t    = threadIdx.x;                // 0..127 = chunk within half
    const int pix0 = blockIdx.x * 2;             // even; never straddles image
    const int b    = pix0 / HW;
    const int hw0  = pix0 - b * HW;

    // pattern indices for both pixels (one 8B load, warp-uniform)
    const int2 pi = __ldg(reinterpret_cast<const int2*>(pidx + pix0));

    const long long base = (long long)pix0 * D4;

    // ---- front-batched x loads: 2 pixels x (spatial chunk, pattern chunk) ----
    float4 xs0 = __ldg(&x4[base + 0 * D4 + t]);           // pix0, c4 = t
    float4 xp0 = __ldg(&x4[base + 0 * D4 + HALF4 + t]);   // pix0, c4 = t+128
    float4 xs1 = __ldg(&x4[base + 1 * D4 + t]);           // pix1, c4 = t
    float4 xp1 = __ldg(&x4[base + 1 * D4 + HALF4 + t]);   // pix1, c4 = t+128

    // ---- PE loads (L2-resident) ----
    const float4* s = sp4 + (long long)hw0 * HALF4 + t;
    float4 spe0 = __ldg(&s[0]);                 // spatial_pe[hw0]
    float4 spe1 = __ldg(&s[HALF4]);             // spatial_pe[hw0+1]
    float4 ppe0 = __ldg(&pp4[(long long)(((unsigned)pi.x) % NUM_PAT) * HALF4 + t]);
    float4 ppe1 = __ldg(&pp4[(long long)(((unsigned)pi.y) % NUM_PAT) * HALF4 + t]);

    xs0.x += spe0.x; xs0.y += spe0.y; xs0.z += spe0.z; xs0.w += spe0.w;
    xp0.x += ppe0.x; xp0.y += ppe0.y; xp0.z += ppe0.z; xp0.w += ppe0.w;
    xs1.x += spe1.x; xs1.y += spe1.y; xs1.z += spe1.z; xs1.w += spe1.w;
    xp1.x += ppe1.x; xp1.y += ppe1.y; xp1.z += ppe1.z; xp1.w += ppe1.w;

    out4[base + 0 * D4 + t]         = xs0;
    out4[base + 0 * D4 + HALF4 + t] = xp0;
    out4[base + 1 * D4 + t]         = xs1;
    out4[base + 1 * D4 + HALF4 + t] = xp1;
}

extern "C" void kernel_launch(void* const* d_in, const int* in_sizes, int n_in,
                              void* d_out, int out_size)
{
    const float4* x4   = (const float4*)d_in[0];
    const int*    pidx = (const int*)d_in[1];
    const float4* sp4  = (const float4*)d_in[2];
    const float4* pp4  = (const float4*)d_in[3];
    float4*       out4 = (float4*)d_out;

    pe_add_kernel<<<NBLK, 128>>>(x4, pidx, sp4, pp4, out4);  // 28800 blocks
}